// round 14
// baseline (speedup 1.0000x reference)
#include <cuda_runtime.h>
#include <cuda_fp16.h>
#include <mma.h>
#include <math.h>

using namespace nvcuda;

#define NN 50000
#define EE 800000
#define BB 64
#define HD 128
#define SCAN_BLOCKS 196   // ceil(50000/256)
#define FULL 0xffffffffu

// ---------------- scratch: __device__ globals, device-code access ONLY.
// NEVER pass these as kernel args from host (host shadow addresses are
// silently dereferenceable on GB300 via ATS -> disjoint buffers).
__device__ float  d_h[NN*HD];
__device__ __half d_xph[NN*HD];       // fp16 copy for the gather path
__device__ float  d_asn[NN*4];
__device__ float  d_adn[NN*4];
__device__ float  d_crit[NN];
__device__ float  d_gate[NN];
__device__ int    d_deg[NN];
__device__ int    d_fill[NN];
__device__ int    d_rowptr[NN+1];
__device__ int    d_csrc[EE];
__device__ int    d_bsum[256];
__device__ int    d_boff[256];

__device__ __forceinline__ float lrelu(float v){ return v >= 0.f ? v : 0.2f*v; }
__device__ __forceinline__ float pick4(float4 v, int h){
    float r = v.x;
    r = (h==1) ? v.y : r;
    r = (h==2) ? v.z : r;
    r = (h==3) ? v.w : r;
    return r;
}
// ---- packed fp32x2 helpers (used in gate head) ----
__device__ __forceinline__ unsigned long long packdup(float v){
    unsigned long long r;
    asm("mov.b64 %0, {%1, %2};" : "=l"(r) : "f"(v), "f"(v));
    return r;
}
__device__ __forceinline__ void ffma2(unsigned long long &d, unsigned long long a,
                                      unsigned long long b){
    asm("fma.rn.f32x2 %0, %1, %2, %0;" : "+l"(d) : "l"(a), "l"(b));
}
__device__ __forceinline__ float2 unpack2(unsigned long long v){
    float lo, hi;
    asm("mov.b64 {%0, %1}, %2;" : "=f"(lo), "=f"(hi) : "l"(v));
    return make_float2(lo, hi);
}

// ---------------- init ----------------
__global__ void k_init(){
    int i = blockIdx.x*blockDim.x + threadIdx.x;
    if (i < NN){ d_crit[i] = 0.f; d_deg[i] = 0; d_fill[i] = 0; }
}

// ---------------- edge MLP -> crit, + degree histogram ----------------
__global__ void k_edgemlp(const float* __restrict__ ea, const int* __restrict__ ei,
                          const float* __restrict__ We1, const float* __restrict__ be1,
                          const float* __restrict__ We2, const float* __restrict__ be2){
    int e = blockIdx.x*blockDim.x + threadIdx.x;
    if (e >= EE) return;
    float a0 = ea[2*e], a1 = ea[2*e+1];
    float o0 = be2[0], o1 = be2[1], o2 = be2[2], o3 = be2[3];
    #pragma unroll
    for (int j = 0; j < 16; j++){
        float hv = fmaxf(0.f, a0*We1[j] + a1*We1[16+j] + be1[j]);
        o0 += hv*We2[4*j+0]; o1 += hv*We2[4*j+1];
        o2 += hv*We2[4*j+2]; o3 += hv*We2[4*j+3];
    }
    int dst = ei[EE + e];
    atomicAdd(&d_crit[dst], 0.25f*(o0+o1+o2+o3));
    atomicAdd(&d_deg[dst], 1);
}

// ---------------- 3-phase exclusive scan deg -> rowptr ----------------
__global__ void k_scan1(){
    __shared__ int s[256];
    int tid = threadIdx.x;
    int i = blockIdx.x*256 + tid;
    int v = (i < NN) ? d_deg[i] : 0;
    s[tid] = v; __syncthreads();
    for (int off = 1; off < 256; off <<= 1){
        int t = 0;
        if (tid >= off) t = s[tid-off];
        __syncthreads();
        s[tid] += t;
        __syncthreads();
    }
    if (i < NN) d_rowptr[i] = s[tid] - v;
    if (tid == 255) d_bsum[blockIdx.x] = s[255];
}
__global__ void k_scan2(){
    __shared__ int s[256];
    int tid = threadIdx.x;
    int v = (tid < SCAN_BLOCKS) ? d_bsum[tid] : 0;
    s[tid] = v; __syncthreads();
    for (int off = 1; off < 256; off <<= 1){
        int t = 0;
        if (tid >= off) t = s[tid-off];
        __syncthreads();
        s[tid] += t;
        __syncthreads();
    }
    d_boff[tid] = s[tid] - v;
}
__global__ void k_scan3(){
    int i = blockIdx.x*blockDim.x + threadIdx.x;
    if (i < NN) d_rowptr[i] += d_boff[i >> 8];
    if (i == 0) d_rowptr[NN] = EE;
}
__global__ void k_scatter(const int* __restrict__ ei){
    int e = blockIdx.x*blockDim.x + threadIdx.x;
    if (e >= EE) return;
    int src = ei[e], dst = ei[EE + e];
    int p = atomicAdd(&d_fill[dst], 1);
    d_csrc[d_rowptr[dst] + p] = src;
}

// ---------------- TF32 tensor-core GEMM + fused attention epilogue --------
// C[64,128] = A[64,128] @ B[128,128] per block; 256 threads = 8 warps,
// each warp a 16x64 tile (4 m16n16k8 accumulators). A tf32-staged in smem,
// C written back into the same smem. Epilogue: thread = (row, head).
// SRC: 0 = param A, 1 = d_h.  DST: 0 = fp32 d_h, 1 = fp16 d_xph.
template<int SRC, int DST, int BIAS, int ATTN>
__global__ void k_gemm128(const float* __restrict__ Ap, const float* __restrict__ B,
                          const float* __restrict__ bias,
                          const float* __restrict__ asrc, const float* __restrict__ adst){
    __shared__ float As[64*128];             // 32KB: A staging, then C tile
    const int tid = threadIdx.x;             // 256
    const int row0 = blockIdx.x * 64;
    const float* A = SRC ? d_h : Ap;

    {   // stage A row-major, tf32-rounded: 4 threads/row, 32 cols each
        int r  = tid >> 2;
        int c0 = (tid & 3) * 32;
        int grow = row0 + r;
        #pragma unroll
        for (int q = 0; q < 8; q++){
            float4 v = make_float4(0.f,0.f,0.f,0.f);
            if (grow < NN) v = *(const float4*)(A + (size_t)grow*128 + c0 + q*4);
            v.x = wmma::__float_to_tf32(v.x);
            v.y = wmma::__float_to_tf32(v.y);
            v.z = wmma::__float_to_tf32(v.z);
            v.w = wmma::__float_to_tf32(v.w);
            *(float4*)(As + r*128 + c0 + q*4) = v;
        }
    }
    __syncthreads();

    const int w  = tid >> 5;
    const int rt = w >> 1;          // row tile (16 rows)
    const int ch = w & 1;           // col half (64 cols)
    wmma::fragment<wmma::accumulator,16,16,8,float> acc[4];
    #pragma unroll
    for (int i = 0; i < 4; i++) wmma::fill_fragment(acc[i], 0.f);

    #pragma unroll
    for (int k = 0; k < 128; k += 8){
        wmma::fragment<wmma::matrix_a,16,16,8,wmma::precision::tf32,wmma::row_major> af;
        wmma::load_matrix_sync(af, As + rt*16*128 + k, 128);
        #pragma unroll
        for (int c = 0; c < 4; c++){
            wmma::fragment<wmma::matrix_b,16,16,8,wmma::precision::tf32,wmma::row_major> bf;
            wmma::load_matrix_sync(bf, B + (size_t)k*128 + ch*64 + c*16, 128);
            wmma::mma_sync(acc[c], af, bf, acc[c]);
        }
    }
    __syncthreads();                 // everyone done reading As
    #pragma unroll
    for (int c = 0; c < 4; c++)
        wmma::store_matrix_sync(As + rt*16*128 + ch*64 + c*16, acc[c], 128,
                                wmma::mem_row_major);
    __syncthreads();

    // epilogue: thread owns (row = tid>>2, head = tid&3) -> 32 cols
    int r  = tid >> 2;
    int hd = tid & 3;
    int grow = row0 + r;
    if (grow >= NN) return;
    const float* cr = As + r*128 + hd*32;
    float vals[32];
    #pragma unroll
    for (int q = 0; q < 8; q++){
        float4 v = *(const float4*)(cr + q*4);
        if (BIAS){
            v.x += bias[hd*32 + q*4 + 0];
            v.y += bias[hd*32 + q*4 + 1];
            v.z += bias[hd*32 + q*4 + 2];
            v.w += bias[hd*32 + q*4 + 3];
        }
        vals[q*4+0] = v.x; vals[q*4+1] = v.y;
        vals[q*4+2] = v.z; vals[q*4+3] = v.w;
    }
    if (DST == 0){
        #pragma unroll
        for (int q = 0; q < 8; q++){
            float4 o;
            o.x = vals[q*4+0]; o.y = vals[q*4+1];
            o.z = vals[q*4+2]; o.w = vals[q*4+3];
            *(float4*)(d_h + (size_t)grow*128 + hd*32 + q*4) = o;
        }
    } else {
        #pragma unroll
        for (int q = 0; q < 4; q++){
            __half2 h0 = __float22half2_rn(make_float2(vals[q*8+0], vals[q*8+1]));
            __half2 h1 = __float22half2_rn(make_float2(vals[q*8+2], vals[q*8+3]));
            __half2 h2 = __float22half2_rn(make_float2(vals[q*8+4], vals[q*8+5]));
            __half2 h3 = __float22half2_rn(make_float2(vals[q*8+6], vals[q*8+7]));
            uint4 pk;
            pk.x = *(unsigned*)&h0; pk.y = *(unsigned*)&h1;
            pk.z = *(unsigned*)&h2; pk.w = *(unsigned*)&h3;
            *(uint4*)(d_xph + (size_t)grow*128 + hd*32 + q*8) = pk;
        }
    }
    if (ATTN){
        float ps = 0.f, pd = 0.f;
        #pragma unroll
        for (int j = 0; j < 32; j++){
            ps += vals[j]*asrc[hd*32 + j];
            pd += vals[j]*adst[hd*32 + j];
        }
        d_asn[grow*4 + hd] = ps;
        d_adn[grow*4 + hd] = pd;
    }
}

// ---------------- fused GAT aggregation (warp/node, CSR) ------------------
// chunk = 8 edges x 4 heads per lane; 2 shuffles per consumed edge.
// softmax without max-shift is exact here (|e| = O(1), exp cannot overflow).
__global__ void k_agg(const float* __restrict__ bl, const float* __restrict__ lng,
                      const float* __restrict__ lnb){
    int n    = (blockIdx.x*blockDim.x + threadIdx.x) >> 5;
    int lane = threadIdx.x & 31;
    if (n >= NN) return;
    const int hh = lane >> 3;
    const int e8 = lane & 7;

    float4 ad  = *(const float4*)(d_adn + n*4);
    float4 asf = *(const float4*)(d_asn + n*4);
    const float adh = pick4(ad, hh);
    int beg = d_rowptr[n], end = d_rowptr[n+1];

    // self loop
    float p = __expf(lrelu(pick4(asf, hh) + adh));
    float ssum = p;
    uint2 hv = *(const uint2*)(d_xph + (size_t)n*HD + lane*4);
    float2 x01 = __half22float2(*(__half2*)&hv.x);
    float2 x23 = __half22float2(*(__half2*)&hv.y);
    float4 acc;
    acc.x = p*x01.x; acc.y = p*x01.y; acc.z = p*x23.x; acc.w = p*x23.y;

    // edges: 8 per chunk; lane computes exp for (edge e8, head hh)
    for (int base = beg; base < end; base += 8){
        int cnt = end - base; if (cnt > 8) cnt = 8;
        int s = 0; float pe = 0.f;
        if (e8 < cnt){
            s = d_csrc[base + e8];
            pe = __expf(lrelu(d_asn[s*4 + hh] + adh));
        }
        for (int j = 0; j < cnt; j++){
            int   sj = __shfl_sync(FULL, s, j);
            float pv = __shfl_sync(FULL, pe, j | (lane & 24));
            ssum += pv;
            uint2 h2 = *(const uint2*)(d_xph + (size_t)sj*HD + lane*4);
            float2 a01 = __half22float2(*(__half2*)&h2.x);
            float2 a23 = __half22float2(*(__half2*)&h2.y);
            acc.x += pv*a01.x; acc.y += pv*a01.y;
            acc.z += pv*a23.x; acc.w += pv*a23.y;
        }
    }
    float inv = 1.f / (ssum + 1e-16f);

    float4 bl4 = *(const float4*)(bl + lane*4);
    float t0 = acc.x*inv + bl4.x, t1 = acc.y*inv + bl4.y;
    float t2 = acc.z*inv + bl4.z, t3 = acc.w*inv + bl4.w;

    float ls = t0 + t1 + t2 + t3;
    #pragma unroll
    for (int o = 16; o; o >>= 1) ls += __shfl_xor_sync(FULL, ls, o);
    float mu = ls * (1.f/128.f);
    float dx0 = t0-mu, dx1 = t1-mu, dx2 = t2-mu, dx3 = t3-mu;
    float vq = dx0*dx0 + dx1*dx1 + dx2*dx2 + dx3*dx3;
    #pragma unroll
    for (int o = 16; o; o >>= 1) vq += __shfl_xor_sync(FULL, vq, o);
    float rstd = rsqrtf(vq*(1.f/128.f) + 1e-5f);

    float4 g4 = *(const float4*)(lng + lane*4);
    float4 b4 = *(const float4*)(lnb + lane*4);
    float cr  = d_crit[n];
    float4 hold = *(float4*)(d_h + (size_t)n*HD + lane*4);
    float4 outv;
    outv.x = dx0*rstd*g4.x + b4.x + cr + hold.x;
    outv.y = dx1*rstd*g4.y + b4.y + cr + hold.y;
    outv.z = dx2*rstd*g4.z + b4.z + cr + hold.z;
    outv.w = dx3*rstd*g4.w + b4.w + cr + hold.w;
    *(float4*)(d_h + (size_t)n*HD + lane*4) = outv;
}

// ---------------- fused gate head: d_gate = tanh(h@Wg1+bg1)·Wg2 + bg2 -----
__global__ void k_gatehead(const float* __restrict__ Wg1, const float* __restrict__ bg1,
                           const float* __restrict__ Wg2, const float* __restrict__ bg2){
    __shared__ float As[128][64];
    const int tid = threadIdx.x;
    const int tx = tid & 31, ty = tid >> 5;
    const int row0 = blockIdx.x * 64;

    {   // stage d_h transposed
        int r = tid >> 1;
        int halfk = (tid & 1) * 64;
        int grow = row0 + r;
        #pragma unroll
        for (int q = 0; q < 16; q++){
            float4 v = make_float4(0.f,0.f,0.f,0.f);
            if (grow < NN) v = *(const float4*)(d_h + (size_t)grow*128 + halfk + q*4);
            As[halfk + q*4 + 0][r] = v.x;
            As[halfk + q*4 + 1][r] = v.y;
            As[halfk + q*4 + 2][r] = v.z;
            As[halfk + q*4 + 3][r] = v.w;
        }
    }
    __syncthreads();

    unsigned long long acc2[8][2];
    #pragma unroll
    for (int r = 0; r < 8; r++){ acc2[r][0] = 0ull; acc2[r][1] = 0ull; }
    const int col = tx * 2;
    #pragma unroll 2
    for (int k = 0; k < 128; k++){
        float2 b = *(const float2*)(Wg1 + (size_t)k*64 + col);
        unsigned long long b0 = packdup(b.x), b1 = packdup(b.y);
        const unsigned long long* ap = (const unsigned long long*)&As[k][ty*16];
        #pragma unroll
        for (int r = 0; r < 8; r++){
            unsigned long long a = ap[r];
            ffma2(acc2[r][0], a, b0);
            ffma2(acc2[r][1], a, b1);
        }
    }
    float b0 = bg1[col], b1 = bg1[col+1];
    float w0 = Wg2[col], w1 = Wg2[col+1];
    float bg = bg2[0];
    #pragma unroll
    for (int r = 0; r < 8; r++){
        float2 c0 = unpack2(acc2[r][0]);
        float2 c1 = unpack2(acc2[r][1]);
        float glo = tanhf(c0.x + b0)*w0 + tanhf(c1.x + b1)*w1;
        float ghi = tanhf(c0.y + b0)*w0 + tanhf(c1.y + b1)*w1;
        #pragma unroll
        for (int o = 16; o; o >>= 1){
            glo += __shfl_xor_sync(FULL, glo, o);
            ghi += __shfl_xor_sync(FULL, ghi, o);
        }
        if (tx == 0){
            int row = row0 + ty*16 + 2*r;
            if (row < NN)     d_gate[row]   = glo + bg;
            if (row+1 < NN)   d_gate[row+1] = ghi + bg;
        }
    }
}

// ---------------- pooling: one block per graph (batch sorted) -------------
__device__ __forceinline__ int lbound(const int* a, int n, int key){
    int lo = 0, hi = n;
    while (lo < hi){ int mid = (lo+hi)>>1; if (a[mid] < key) lo = mid+1; else hi = mid; }
    return lo;
}
__global__ void k_pool(const int* __restrict__ batch, float* __restrict__ out){
    int b = blockIdx.x, c = threadIdx.x;
    int lo = lbound(batch, NN, b), hi = lbound(batch, NN, b+1);
    float m = -3.402823e38f;
    for (int n = lo; n < hi; n++) m = fmaxf(m, d_gate[n]);
    float acc = 0.f, ps = 0.f;
    for (int n = lo; n < hi; n++){
        float p = expf(d_gate[n] - m);
        ps += p; acc += p * d_h[(size_t)n*HD + c];
    }
    out[b*HD + c] = acc / (ps + 1e-16f);
}

// ---------------- launch ----------------
extern "C" void kernel_launch(void* const* d_in, const int* in_sizes, int n_in,
                              void* d_out, int out_size){
    const float* x    = (const float*)d_in[0];
    const float* ea   = (const float*)d_in[1];
    const float* Win  = (const float*)d_in[2];
    const float* b_in = (const float*)d_in[3];
    const float* We1  = (const float*)d_in[4];
    const float* be1  = (const float*)d_in[5];
    const float* We2  = (const float*)d_in[6];
    const float* be2  = (const float*)d_in[7];
    const float* Wl   = (const float*)d_in[8];
    const float* asrc = (const float*)d_in[9];
    const float* adst = (const float*)d_in[10];
    const float* bl   = (const float*)d_in[11];
    const float* lng  = (const float*)d_in[12];
    const float* lnb  = (const float*)d_in[13];
    const float* Wg1  = (const float*)d_in[14];
    const float* bg1  = (const float*)d_in[15];
    const float* Wg2  = (const float*)d_in[16];
    const float* bg2  = (const float*)d_in[17];
    const int*   ei   = (const int*)d_in[18];
    const int*   batch= (const int*)d_in[19];
    float* out = (float*)d_out;

    const int EB  = (EE + 255)/256;
    const int NWB = (NN*32 + 255)/256;
    const int GB  = (NN + 63)/64;

    k_init<<<(NN+255)/256, 256>>>();
    k_edgemlp<<<EB, 256>>>(ea, ei, We1, be1, We2, be2);
    k_gemm128<0,0,1,0><<<GB, 256>>>(x, Win, b_in, (const float*)0, (const float*)0);
    k_gemm128<1,1,0,1><<<GB, 256>>>((const float*)0, Wl, (const float*)0, asrc, adst);

    // CSR build (independent of GEMMs)
    k_scan1<<<SCAN_BLOCKS, 256>>>();
    k_scan2<<<1, 256>>>();
    k_scan3<<<SCAN_BLOCKS, 256>>>();
    k_scatter<<<EB, 256>>>(ei);

    k_agg<<<NWB, 256>>>(bl, lng, lnb);
    for (int l = 1; l < 4; l++){
        k_gemm128<1,1,0,1><<<GB, 256>>>((const float*)0, Wl + (size_t)l*HD*HD,
                                        (const float*)0, asrc + l*128, adst + l*128);
        k_agg<<<NWB, 256>>>(bl + l*HD, lng + l*HD, lnb + l*HD);
    }

    k_gatehead<<<GB, 128>>>(Wg1, bg1, Wg2, bg2);
    k_pool<<<BB, 128>>>(batch, out);
}

// round 15
// speedup vs baseline: 1.1521x; 1.1521x over previous
#include <cuda_runtime.h>
#include <cuda_fp16.h>
#include <math.h>

#define NN 50000
#define EE 800000
#define BB 64
#define HD 128
#define SCAN_BLOCKS 196   // ceil(50000/256)
#define FULL 0xffffffffu

// ---------------- scratch: __device__ globals, device-code access ONLY.
// NEVER pass these as kernel args from host (host shadow addresses are
// silently dereferenceable on GB300 via ATS -> disjoint buffers).
__device__ float  d_h[NN*HD];
__device__ __half d_xph[NN*HD];       // fp16 copy for the gather path
__device__ float  d_asn[NN*4];
__device__ float  d_adn[NN*4];
__device__ float  d_crit[NN];
__device__ float  d_gate[NN];
__device__ int    d_deg[NN];
__device__ int    d_fill[NN];
__device__ int    d_rowptr[NN+1];
__device__ int    d_csrc[EE];
__device__ int    d_bsum[256];
__device__ int    d_boff[256];

__device__ __forceinline__ float lrelu(float v){ return v >= 0.f ? v : 0.2f*v; }
__device__ __forceinline__ float pick4(float4 v, int h){
    float r = v.x;
    r = (h==1) ? v.y : r;
    r = (h==2) ? v.z : r;
    r = (h==3) ? v.w : r;
    return r;
}
// ---- packed fp32x2 helpers (FFMA2: Blackwell-only, PTX fma.rn.f32x2) ----
__device__ __forceinline__ unsigned long long packdup(float v){
    unsigned long long r;
    asm("mov.b64 %0, {%1, %2};" : "=l"(r) : "f"(v), "f"(v));
    return r;
}
__device__ __forceinline__ void ffma2(unsigned long long &d, unsigned long long a,
                                      unsigned long long b){
    asm("fma.rn.f32x2 %0, %1, %2, %0;" : "+l"(d) : "l"(a), "l"(b));
}
__device__ __forceinline__ float2 unpack2(unsigned long long v){
    float lo, hi;
    asm("mov.b64 {%0, %1}, %2;" : "=f"(lo), "=f"(hi) : "l"(v));
    return make_float2(lo, hi);
}

// ---------------- init ----------------
__global__ void k_init(){
    int i = blockIdx.x*blockDim.x + threadIdx.x;
    if (i < NN){ d_crit[i] = 0.f; d_deg[i] = 0; d_fill[i] = 0; }
}

// ---------------- edge MLP -> crit, + degree histogram ----------------
__global__ void k_edgemlp(const float* __restrict__ ea, const int* __restrict__ ei,
                          const float* __restrict__ We1, const float* __restrict__ be1,
                          const float* __restrict__ We2, const float* __restrict__ be2){
    int e = blockIdx.x*blockDim.x + threadIdx.x;
    if (e >= EE) return;
    float a0 = ea[2*e], a1 = ea[2*e+1];
    float o0 = be2[0], o1 = be2[1], o2 = be2[2], o3 = be2[3];
    #pragma unroll
    for (int j = 0; j < 16; j++){
        float hv = fmaxf(0.f, a0*We1[j] + a1*We1[16+j] + be1[j]);
        o0 += hv*We2[4*j+0]; o1 += hv*We2[4*j+1];
        o2 += hv*We2[4*j+2]; o3 += hv*We2[4*j+3];
    }
    int dst = ei[EE + e];
    atomicAdd(&d_crit[dst], 0.25f*(o0+o1+o2+o3));
    atomicAdd(&d_deg[dst], 1);
}

// ---------------- 3-phase exclusive scan deg -> rowptr ----------------
__global__ void k_scan1(){
    __shared__ int s[256];
    int tid = threadIdx.x;
    int i = blockIdx.x*256 + tid;
    int v = (i < NN) ? d_deg[i] : 0;
    s[tid] = v; __syncthreads();
    for (int off = 1; off < 256; off <<= 1){
        int t = 0;
        if (tid >= off) t = s[tid-off];
        __syncthreads();
        s[tid] += t;
        __syncthreads();
    }
    if (i < NN) d_rowptr[i] = s[tid] - v;
    if (tid == 255) d_bsum[blockIdx.x] = s[255];
}
__global__ void k_scan2(){
    __shared__ int s[256];
    int tid = threadIdx.x;
    int v = (tid < SCAN_BLOCKS) ? d_bsum[tid] : 0;
    s[tid] = v; __syncthreads();
    for (int off = 1; off < 256; off <<= 1){
        int t = 0;
        if (tid >= off) t = s[tid-off];
        __syncthreads();
        s[tid] += t;
        __syncthreads();
    }
    d_boff[tid] = s[tid] - v;
}
__global__ void k_scan3(){
    int i = blockIdx.x*blockDim.x + threadIdx.x;
    if (i < NN) d_rowptr[i] += d_boff[i >> 8];
    if (i == 0) d_rowptr[NN] = EE;
}
__global__ void k_scatter(const int* __restrict__ ei){
    int e = blockIdx.x*blockDim.x + threadIdx.x;
    if (e >= EE) return;
    int src = ei[e], dst = ei[EE + e];
    int p = atomicAdd(&d_fill[dst], 1);
    d_csrc[d_rowptr[dst] + p] = src;
}

// ---------------- tiled GEMM (FFMA2) + fused attention coefficients -------
// C[M,128] = A[M,128] @ B[128,128] (+bias). 128 threads, 64 rows/block.
// Thread tile: 8 row-pairs x 4 cols, packed fp32x2 accumulators.
// A pairs loaded as broadcast LDS.128 (addresses depend only on warp id);
// B software-prefetched one k ahead to break the LDG->FMA chain.
// SRC: 0 = param A, 1 = d_h.  DST: 0 = fp32 d_h, 1 = fp16 d_xph.
template<int SRC, int DST, int BIAS, int ATTN>
__global__ void k_gemm128(const float* __restrict__ Ap, const float* __restrict__ B,
                          const float* __restrict__ bias,
                          const float* __restrict__ asrc, const float* __restrict__ adst){
    __shared__ float As[128][64];            // [k][row] 32KB; rows contiguous
    const int tid = threadIdx.x;             // 128
    const int tx = tid & 31, ty = tid >> 5;
    const int row0 = blockIdx.x * 64;
    const float* A = SRC ? d_h : Ap;

    {   // stage A transposed: 2 threads per row, 64 floats each
        int r = tid >> 1;
        int halfk = (tid & 1) * 64;
        int grow = row0 + r;
        #pragma unroll
        for (int q = 0; q < 16; q++){
            float4 v = make_float4(0.f,0.f,0.f,0.f);
            if (grow < NN) v = *(const float4*)(A + (size_t)grow*128 + halfk + q*4);
            As[halfk + q*4 + 0][r] = v.x;
            As[halfk + q*4 + 1][r] = v.y;
            As[halfk + q*4 + 2][r] = v.z;
            As[halfk + q*4 + 3][r] = v.w;
        }
    }
    __syncthreads();

    unsigned long long acc2[8][4];           // [row-pair][col], fp32x2
    #pragma unroll
    for (int r = 0; r < 8; r++)
        #pragma unroll
        for (int c = 0; c < 4; c++) acc2[r][c] = 0ull;

    const int col = tx * 4;
    float4 bnx = *(const float4*)(B + col);          // prefetch k=0
    #pragma unroll 2
    for (int k = 0; k < 128; k++){
        float4 b = bnx;
        if (k < 127) bnx = *(const float4*)(B + (size_t)(k+1)*128 + col);
        unsigned long long b0 = packdup(b.x), b1 = packdup(b.y);
        unsigned long long b2 = packdup(b.z), b3 = packdup(b.w);
        const ulonglong2* ap = (const ulonglong2*)&As[k][ty*16];   // 4 x LDS.128
        #pragma unroll
        for (int r4 = 0; r4 < 4; r4++){
            ulonglong2 a2 = ap[r4];
            ffma2(acc2[2*r4  ][0], a2.x, b0);
            ffma2(acc2[2*r4  ][1], a2.x, b1);
            ffma2(acc2[2*r4  ][2], a2.x, b2);
            ffma2(acc2[2*r4  ][3], a2.x, b3);
            ffma2(acc2[2*r4+1][0], a2.y, b0);
            ffma2(acc2[2*r4+1][1], a2.y, b1);
            ffma2(acc2[2*r4+1][2], a2.y, b2);
            ffma2(acc2[2*r4+1][3], a2.y, b3);
        }
    }

    // unpack to per-row scalars
    float acc[16][4];
    #pragma unroll
    for (int r = 0; r < 8; r++)
        #pragma unroll
        for (int c = 0; c < 4; c++){
            float2 p = unpack2(acc2[r][c]);
            acc[2*r  ][c] = p.x;
            acc[2*r+1][c] = p.y;
        }

    float4 bv = make_float4(0.f,0.f,0.f,0.f);
    if (BIAS) bv = *(const float4*)(bias + col);
    #pragma unroll
    for (int r = 0; r < 16; r++){
        int row = row0 + ty*16 + r;
        if (row < NN){
            float o0 = acc[r][0] + bv.x, o1 = acc[r][1] + bv.y;
            float o2 = acc[r][2] + bv.z, o3 = acc[r][3] + bv.w;
            if (DST == 0){
                float4 o; o.x = o0; o.y = o1; o.z = o2; o.w = o3;
                *(float4*)(d_h + (size_t)row*128 + col) = o;
            } else {
                __half2 h01 = __float22half2_rn(make_float2(o0, o1));
                __half2 h23 = __float22half2_rn(make_float2(o2, o3));
                uint2 pk;
                pk.x = *(unsigned*)&h01; pk.y = *(unsigned*)&h23;
                *(uint2*)(d_xph + (size_t)row*128 + col) = pk;
            }
        }
    }
    if (ATTN){
        float4 avs = *(const float4*)(asrc + col);
        float4 avd = *(const float4*)(adst + col);
        const int head = tx >> 3;
        #pragma unroll
        for (int r = 0; r < 16; r++){
            float ps = acc[r][0]*avs.x + acc[r][1]*avs.y
                     + acc[r][2]*avs.z + acc[r][3]*avs.w;
            float pd = acc[r][0]*avd.x + acc[r][1]*avd.y
                     + acc[r][2]*avd.z + acc[r][3]*avd.w;
            #pragma unroll
            for (int o = 4; o; o >>= 1){
                ps += __shfl_xor_sync(FULL, ps, o, 8);
                pd += __shfl_xor_sync(FULL, pd, o, 8);
            }
            if ((tx & 7) == 0){
                int row = row0 + ty*16 + r;
                if (row < NN){
                    d_asn[row*4 + head] = ps;
                    d_adn[row*4 + head] = pd;
                }
            }
        }
    }
}

// ---------------- fused GAT aggregation (warp/node, CSR) ------------------
// chunk = 8 edges x 4 heads per lane; 2 shuffles per consumed edge.
// softmax without max-shift is exact here (|e| = O(1), exp cannot overflow).
__global__ void k_agg(const float* __restrict__ bl, const float* __restrict__ lng,
                      const float* __restrict__ lnb){
    int n    = (blockIdx.x*blockDim.x + threadIdx.x) >> 5;
    int lane = threadIdx.x & 31;
    if (n >= NN) return;
    const int hh = lane >> 3;
    const int e8 = lane & 7;

    float4 ad  = *(const float4*)(d_adn + n*4);
    float4 asf = *(const float4*)(d_asn + n*4);
    const float adh = pick4(ad, hh);
    int beg = d_rowptr[n], end = d_rowptr[n+1];

    // self loop
    float p = __expf(lrelu(pick4(asf, hh) + adh));
    float ssum = p;
    uint2 hv = *(const uint2*)(d_xph + (size_t)n*HD + lane*4);
    float2 x01 = __half22float2(*(__half2*)&hv.x);
    float2 x23 = __half22float2(*(__half2*)&hv.y);
    float4 acc;
    acc.x = p*x01.x; acc.y = p*x01.y; acc.z = p*x23.x; acc.w = p*x23.y;

    // edges: 8 per chunk; lane computes exp for (edge e8, head hh)
    for (int base = beg; base < end; base += 8){
        int cnt = end - base; if (cnt > 8) cnt = 8;
        int s = 0; float pe = 0.f;
        if (e8 < cnt){
            s = d_csrc[base + e8];
            pe = __expf(lrelu(d_asn[s*4 + hh] + adh));
        }
        for (int j = 0; j < cnt; j++){
            int   sj = __shfl_sync(FULL, s, j);
            float pv = __shfl_sync(FULL, pe, j | (lane & 24));
            ssum += pv;
            uint2 h2 = *(const uint2*)(d_xph + (size_t)sj*HD + lane*4);
            float2 a01 = __half22float2(*(__half2*)&h2.x);
            float2 a23 = __half22float2(*(__half2*)&h2.y);
            acc.x += pv*a01.x; acc.y += pv*a01.y;
            acc.z += pv*a23.x; acc.w += pv*a23.y;
        }
    }
    float inv = 1.f / (ssum + 1e-16f);

    float4 bl4 = *(const float4*)(bl + lane*4);
    float t0 = acc.x*inv + bl4.x, t1 = acc.y*inv + bl4.y;
    float t2 = acc.z*inv + bl4.z, t3 = acc.w*inv + bl4.w;

    float ls = t0 + t1 + t2 + t3;
    #pragma unroll
    for (int o = 16; o; o >>= 1) ls += __shfl_xor_sync(FULL, ls, o);
    float mu = ls * (1.f/128.f);
    float dx0 = t0-mu, dx1 = t1-mu, dx2 = t2-mu, dx3 = t3-mu;
    float vq = dx0*dx0 + dx1*dx1 + dx2*dx2 + dx3*dx3;
    #pragma unroll
    for (int o = 16; o; o >>= 1) vq += __shfl_xor_sync(FULL, vq, o);
    float rstd = rsqrtf(vq*(1.f/128.f) + 1e-5f);

    float4 g4 = *(const float4*)(lng + lane*4);
    float4 b4 = *(const float4*)(lnb + lane*4);
    float cr  = d_crit[n];
    float4 hold = *(float4*)(d_h + (size_t)n*HD + lane*4);
    float4 outv;
    outv.x = dx0*rstd*g4.x + b4.x + cr + hold.x;
    outv.y = dx1*rstd*g4.y + b4.y + cr + hold.y;
    outv.z = dx2*rstd*g4.z + b4.z + cr + hold.z;
    outv.w = dx3*rstd*g4.w + b4.w + cr + hold.w;
    *(float4*)(d_h + (size_t)n*HD + lane*4) = outv;
}

// ---------------- fused gate head: d_gate = tanh(h@Wg1+bg1)·Wg2 + bg2 -----
__global__ void k_gatehead(const float* __restrict__ Wg1, const float* __restrict__ bg1,
                           const float* __restrict__ Wg2, const float* __restrict__ bg2){
    __shared__ float As[128][64];
    const int tid = threadIdx.x;
    const int tx = tid & 31, ty = tid >> 5;
    const int row0 = blockIdx.x * 64;

    {   // stage d_h transposed
        int r = tid >> 1;
        int halfk = (tid & 1) * 64;
        int grow = row0 + r;
        #pragma unroll
        for (int q = 0; q < 16; q++){
            float4 v = make_float4(0.f,0.f,0.f,0.f);
            if (grow < NN) v = *(const float4*)(d_h + (size_t)grow*128 + halfk + q*4);
            As[halfk + q*4 + 0][r] = v.x;
            As[halfk + q*4 + 1][r] = v.y;
            As[halfk + q*4 + 2][r] = v.z;
            As[halfk + q*4 + 3][r] = v.w;
        }
    }
    __syncthreads();

    unsigned long long acc2[8][2];
    #pragma unroll
    for (int r = 0; r < 8; r++){ acc2[r][0] = 0ull; acc2[r][1] = 0ull; }
    const int col = tx * 2;
    #pragma unroll 2
    for (int k = 0; k < 128; k++){
        float2 b = *(const float2*)(Wg1 + (size_t)k*64 + col);
        unsigned long long b0 = packdup(b.x), b1 = packdup(b.y);
        const ulonglong2* ap = (const ulonglong2*)&As[k][ty*16];
        #pragma unroll
        for (int r4 = 0; r4 < 4; r4++){
            ulonglong2 a2 = ap[r4];
            ffma2(acc2[2*r4  ][0], a2.x, b0);
            ffma2(acc2[2*r4  ][1], a2.x, b1);
            ffma2(acc2[2*r4+1][0], a2.y, b0);
            ffma2(acc2[2*r4+1][1], a2.y, b1);
        }
    }
    float b0 = bg1[col], b1 = bg1[col+1];
    float w0 = Wg2[col], w1 = Wg2[col+1];
    float bg = bg2[0];
    #pragma unroll
    for (int r = 0; r < 8; r++){
        float2 c0 = unpack2(acc2[r][0]);
        float2 c1 = unpack2(acc2[r][1]);
        float glo = tanhf(c0.x + b0)*w0 + tanhf(c1.x + b1)*w1;
        float ghi = tanhf(c0.y + b0)*w0 + tanhf(c1.y + b1)*w1;
        #pragma unroll
        for (int o = 16; o; o >>= 1){
            glo += __shfl_xor_sync(FULL, glo, o);
            ghi += __shfl_xor_sync(FULL, ghi, o);
        }
        if (tx == 0){
            int row = row0 + ty*16 + 2*r;
            if (row < NN)     d_gate[row]   = glo + bg;
            if (row+1 < NN)   d_gate[row+1] = ghi + bg;
        }
    }
}

// ---------------- pooling: one block per graph (batch sorted) -------------
__device__ __forceinline__ int lbound(const int* a, int n, int key){
    int lo = 0, hi = n;
    while (lo < hi){ int mid = (lo+hi)>>1; if (a[mid] < key) lo = mid+1; else hi = mid; }
    return lo;
}
__global__ void k_pool(const int* __restrict__ batch, float* __restrict__ out){
    int b = blockIdx.x, c = threadIdx.x;
    int lo = lbound(batch, NN, b), hi = lbound(batch, NN, b+1);
    float m = -3.402823e38f;
    for (int n = lo; n < hi; n++) m = fmaxf(m, d_gate[n]);
    float acc = 0.f, ps = 0.f;
    for (int n = lo; n < hi; n++){
        float p = expf(d_gate[n] - m);
        ps += p; acc += p * d_h[(size_t)n*HD + c];
    }
    out[b*HD + c] = acc / (ps + 1e-16f);
}

// ---------------- launch ----------------
extern "C" void kernel_launch(void* const* d_in, const int* in_sizes, int n_in,
                              void* d_out, int out_size){
    const float* x    = (const float*)d_in[0];
    const float* ea   = (const float*)d_in[1];
    const float* Win  = (const float*)d_in[2];
    const float* b_in = (const float*)d_in[3];
    const float* We1  = (const float*)d_in[4];
    const float* be1  = (const float*)d_in[5];
    const float* We2  = (const float*)d_in[6];
    const float* be2  = (const float*)d_in[7];
    const float* Wl   = (const float*)d_in[8];
    const float* asrc = (const float*)d_in[9];
    const float* adst = (const float*)d_in[10];
    const float* bl   = (const float*)d_in[11];
    const float* lng  = (const float*)d_in[12];
    const float* lnb  = (const float*)d_in[13];
    const float* Wg1  = (const float*)d_in[14];
    const float* bg1  = (const float*)d_in[15];
    const float* Wg2  = (const float*)d_in[16];
    const float* bg2  = (const float*)d_in[17];
    const int*   ei   = (const int*)d_in[18];
    const int*   batch= (const int*)d_in[19];
    float* out = (float*)d_out;

    const int EB  = (EE + 255)/256;
    const int NWB = (NN*32 + 255)/256;
    const int GB  = (NN + 63)/64;

    k_init<<<(NN+255)/256, 256>>>();
    k_edgemlp<<<EB, 256>>>(ea, ei, We1, be1, We2, be2);
    k_gemm128<0,0,1,0><<<GB, 128>>>(x, Win, b_in, (const float*)0, (const float*)0);
    k_gemm128<1,1,0,1><<<GB, 128>>>((const float*)0, Wl, (const float*)0, asrc, adst);

    // CSR build (independent of GEMMs)
    k_scan1<<<SCAN_BLOCKS, 256>>>();
    k_scan2<<<1, 256>>>();
    k_scan3<<<SCAN_BLOCKS, 256>>>();
    k_scatter<<<EB, 256>>>(ei);

    k_agg<<<NWB, 256>>>(bl, lng, lnb);
    for (int l = 1; l < 4; l++){
        k_gemm128<1,1,0,1><<<GB, 128>>>((const float*)0, Wl + (size_t)l*HD*HD,
                                        (const float*)0, asrc + l*128, adst + l*128);
        k_agg<<<NWB, 256>>>(bl + l*HD, lng + l*HD, lnb + l*HD);
    }

    k_gatehead<<<GB, 128>>>(Wg1, bg1, Wg2, bg2);
    k_pool<<<BB, 128>>>(batch, out);
}

// round 16
// speedup vs baseline: 1.1920x; 1.0346x over previous
#include <cuda_runtime.h>
#include <cuda_fp16.h>
#include <math.h>

#define NN 50000
#define EE 800000
#define BB 64
#define HD 128
#define SCAN_BLOCKS 196   // ceil(50000/256)
#define FULL 0xffffffffu

// ---------------- scratch: __device__ globals, device-code access ONLY.
// NEVER pass these as kernel args from host (host shadow addresses are
// silently dereferenceable on GB300 via ATS -> disjoint buffers).
__device__ float  d_h[NN*HD];
__device__ __half d_xph[NN*HD];       // fp16 copy for the gather path
__device__ float  d_asn[NN*4];
__device__ float  d_adn[NN*4];
__device__ float  d_crit[NN];
__device__ float  d_gate[NN];
__device__ int    d_deg[NN];
__device__ int    d_fill[NN];
__device__ int    d_rowptr[NN+1];
__device__ int    d_csrc[EE];
__device__ int    d_bsum[256];
__device__ int    d_boff[256];

__device__ __forceinline__ float lrelu(float v){ return v >= 0.f ? v : 0.2f*v; }
__device__ __forceinline__ float pick4(float4 v, int h){
    float r = v.x;
    r = (h==1) ? v.y : r;
    r = (h==2) ? v.z : r;
    r = (h==3) ? v.w : r;
    return r;
}
// ---- packed fp32x2 helpers (FFMA2: Blackwell-only, PTX fma.rn.f32x2) ----
__device__ __forceinline__ unsigned long long packdup(float v){
    unsigned long long r;
    asm("mov.b64 %0, {%1, %2};" : "=l"(r) : "f"(v), "f"(v));
    return r;
}
__device__ __forceinline__ void ffma2(unsigned long long &d, unsigned long long a,
                                      unsigned long long b){
    asm("fma.rn.f32x2 %0, %1, %2, %0;" : "+l"(d) : "l"(a), "l"(b));
}
__device__ __forceinline__ float2 unpack2(unsigned long long v){
    float lo, hi;
    asm("mov.b64 {%0, %1}, %2;" : "=f"(lo), "=f"(hi) : "l"(v));
    return make_float2(lo, hi);
}

// ---------------- init ----------------
__global__ void k_init(){
    int i = blockIdx.x*blockDim.x + threadIdx.x;
    if (i < NN){ d_crit[i] = 0.f; d_deg[i] = 0; d_fill[i] = 0; }
}

// ---------------- edge MLP -> crit, + degree histogram ----------------
// mean over heads collapsed into We2 row-means: o = sum_j relu(z_j)*wbar_j + bbar
__global__ void k_edgemlp(const float* __restrict__ ea, const int* __restrict__ ei,
                          const float* __restrict__ We1, const float* __restrict__ be1,
                          const float* __restrict__ We2, const float* __restrict__ be2){
    __shared__ float w1a[16], w1b[16], b1[16], wbar[16];
    __shared__ float bbar;
    int t = threadIdx.x;
    if (t < 16){
        w1a[t] = We1[t];
        w1b[t] = We1[16 + t];
        b1[t]  = be1[t];
        wbar[t] = 0.25f*(We2[4*t] + We2[4*t+1] + We2[4*t+2] + We2[4*t+3]);
    }
    if (t == 16) bbar = 0.25f*(be2[0] + be2[1] + be2[2] + be2[3]);
    __syncthreads();
    int e = blockIdx.x*blockDim.x + t;
    if (e >= EE) return;
    float a0 = ea[2*e], a1 = ea[2*e+1];
    float o = bbar;
    #pragma unroll
    for (int j = 0; j < 16; j++)
        o += fmaxf(0.f, a0*w1a[j] + a1*w1b[j] + b1[j]) * wbar[j];
    int dst = ei[EE + e];
    atomicAdd(&d_crit[dst], o);
    atomicAdd(&d_deg[dst], 1);
}

// ---------------- 3-phase exclusive scan deg -> rowptr ----------------
__global__ void k_scan1(){
    __shared__ int s[256];
    int tid = threadIdx.x;
    int i = blockIdx.x*256 + tid;
    int v = (i < NN) ? d_deg[i] : 0;
    s[tid] = v; __syncthreads();
    for (int off = 1; off < 256; off <<= 1){
        int t = 0;
        if (tid >= off) t = s[tid-off];
        __syncthreads();
        s[tid] += t;
        __syncthreads();
    }
    if (i < NN) d_rowptr[i] = s[tid] - v;
    if (tid == 255) d_bsum[blockIdx.x] = s[255];
}
__global__ void k_scan2(){
    __shared__ int s[256];
    int tid = threadIdx.x;
    int v = (tid < SCAN_BLOCKS) ? d_bsum[tid] : 0;
    s[tid] = v; __syncthreads();
    for (int off = 1; off < 256; off <<= 1){
        int t = 0;
        if (tid >= off) t = s[tid-off];
        __syncthreads();
        s[tid] += t;
        __syncthreads();
    }
    d_boff[tid] = s[tid] - v;
}
__global__ void k_scan3(){
    int i = blockIdx.x*blockDim.x + threadIdx.x;
    if (i < NN) d_rowptr[i] += d_boff[i >> 8];
    if (i == 0) d_rowptr[NN] = EE;
}
__global__ void k_scatter(const int* __restrict__ ei){
    int e = blockIdx.x*blockDim.x + threadIdx.x;
    if (e >= EE) return;
    int src = ei[e], dst = ei[EE + e];
    int p = atomicAdd(&d_fill[dst], 1);
    d_csrc[d_rowptr[dst] + p] = src;
}

// ---------------- tiled GEMM (FFMA2) + fused attention coefficients -------
// C[64,128] = A[64,128] @ B[128,128] (+bias). 256 threads = 8 warps;
// warp w owns rows w*8..w*8+7 across all 128 cols. Thread tile: 4 row-pairs
// x 4 cols of packed fp32x2 accumulators (32 regs) -> higher occupancy.
// SRC: 0 = param A, 1 = d_h.  DST: 0 = fp32 d_h, 1 = fp16 d_xph.
template<int SRC, int DST, int BIAS, int ATTN>
__global__ void k_gemm128(const float* __restrict__ Ap, const float* __restrict__ B,
                          const float* __restrict__ bias,
                          const float* __restrict__ asrc, const float* __restrict__ adst){
    __shared__ float As[128][64];            // [k][row] 32KB; rows contiguous
    const int tid = threadIdx.x;             // 256
    const int tx = tid & 31, w = tid >> 5;   // 8 warps
    const int row0 = blockIdx.x * 64;
    const float* A = SRC ? d_h : Ap;

    {   // stage A transposed: 4 threads per row, 32 cols each
        int r  = tid >> 2;
        int c0 = (tid & 3) * 32;
        int grow = row0 + r;
        #pragma unroll
        for (int q = 0; q < 8; q++){
            float4 v = make_float4(0.f,0.f,0.f,0.f);
            if (grow < NN) v = *(const float4*)(A + (size_t)grow*128 + c0 + q*4);
            As[c0 + q*4 + 0][r] = v.x;
            As[c0 + q*4 + 1][r] = v.y;
            As[c0 + q*4 + 2][r] = v.z;
            As[c0 + q*4 + 3][r] = v.w;
        }
    }
    __syncthreads();

    unsigned long long acc2[4][4];           // [row-pair][col], fp32x2
    #pragma unroll
    for (int r = 0; r < 4; r++)
        #pragma unroll
        for (int c = 0; c < 4; c++) acc2[r][c] = 0ull;

    const int col = tx * 4;
    float4 bnx = *(const float4*)(B + col);          // prefetch k=0
    #pragma unroll 4
    for (int k = 0; k < 128; k++){
        float4 b = bnx;
        if (k < 127) bnx = *(const float4*)(B + (size_t)(k+1)*128 + col);
        unsigned long long b0 = packdup(b.x), b1 = packdup(b.y);
        unsigned long long b2 = packdup(b.z), b3 = packdup(b.w);
        const ulonglong2* ap = (const ulonglong2*)&As[k][w*8];   // 2 x LDS.128
        ulonglong2 a01 = ap[0], a23 = ap[1];
        ffma2(acc2[0][0], a01.x, b0); ffma2(acc2[0][1], a01.x, b1);
        ffma2(acc2[0][2], a01.x, b2); ffma2(acc2[0][3], a01.x, b3);
        ffma2(acc2[1][0], a01.y, b0); ffma2(acc2[1][1], a01.y, b1);
        ffma2(acc2[1][2], a01.y, b2); ffma2(acc2[1][3], a01.y, b3);
        ffma2(acc2[2][0], a23.x, b0); ffma2(acc2[2][1], a23.x, b1);
        ffma2(acc2[2][2], a23.x, b2); ffma2(acc2[2][3], a23.x, b3);
        ffma2(acc2[3][0], a23.y, b0); ffma2(acc2[3][1], a23.y, b1);
        ffma2(acc2[3][2], a23.y, b2); ffma2(acc2[3][3], a23.y, b3);
    }

    // unpack to per-row scalars: 8 rows x 4 cols
    float acc[8][4];
    #pragma unroll
    for (int r = 0; r < 4; r++)
        #pragma unroll
        for (int c = 0; c < 4; c++){
            float2 p = unpack2(acc2[r][c]);
            acc[2*r  ][c] = p.x;
            acc[2*r+1][c] = p.y;
        }

    float4 bv = make_float4(0.f,0.f,0.f,0.f);
    if (BIAS) bv = *(const float4*)(bias + col);
    #pragma unroll
    for (int r = 0; r < 8; r++){
        int row = row0 + w*8 + r;
        if (row < NN){
            float o0 = acc[r][0] + bv.x, o1 = acc[r][1] + bv.y;
            float o2 = acc[r][2] + bv.z, o3 = acc[r][3] + bv.w;
            if (DST == 0){
                float4 o; o.x = o0; o.y = o1; o.z = o2; o.w = o3;
                *(float4*)(d_h + (size_t)row*128 + col) = o;
            } else {
                __half2 h01 = __float22half2_rn(make_float2(o0, o1));
                __half2 h23 = __float22half2_rn(make_float2(o2, o3));
                uint2 pk;
                pk.x = *(unsigned*)&h01; pk.y = *(unsigned*)&h23;
                *(uint2*)(d_xph + (size_t)row*128 + col) = pk;
            }
        }
    }
    if (ATTN){
        float4 avs = *(const float4*)(asrc + col);
        float4 avd = *(const float4*)(adst + col);
        const int head = tx >> 3;
        #pragma unroll
        for (int r = 0; r < 8; r++){
            float ps = acc[r][0]*avs.x + acc[r][1]*avs.y
                     + acc[r][2]*avs.z + acc[r][3]*avs.w;
            float pd = acc[r][0]*avd.x + acc[r][1]*avd.y
                     + acc[r][2]*avd.z + acc[r][3]*avd.w;
            #pragma unroll
            for (int o = 4; o; o >>= 1){
                ps += __shfl_xor_sync(FULL, ps, o, 8);
                pd += __shfl_xor_sync(FULL, pd, o, 8);
            }
            if ((tx & 7) == 0){
                int row = row0 + w*8 + r;
                if (row < NN){
                    d_asn[row*4 + head] = ps;
                    d_adn[row*4 + head] = pd;
                }
            }
        }
    }
}

// ---------------- fused GAT aggregation (warp/node, CSR) ------------------
// chunk = 8 edges x 4 heads per lane; 2 shuffles per consumed edge.
// softmax without max-shift is exact here (|e| = O(1), exp cannot overflow).
__global__ void k_agg(const float* __restrict__ bl, const float* __restrict__ lng,
                      const float* __restrict__ lnb){
    int n    = (blockIdx.x*blockDim.x + threadIdx.x) >> 5;
    int lane = threadIdx.x & 31;
    if (n >= NN) return;
    const int hh = lane >> 3;
    const int e8 = lane & 7;

    float4 ad  = *(const float4*)(d_adn + n*4);
    float4 asf = *(const float4*)(d_asn + n*4);
    const float adh = pick4(ad, hh);
    int beg = d_rowptr[n], end = d_rowptr[n+1];

    // self loop
    float p = __expf(lrelu(pick4(asf, hh) + adh));
    float ssum = p;
    uint2 hv = *(const uint2*)(d_xph + (size_t)n*HD + lane*4);
    float2 x01 = __half22float2(*(__half2*)&hv.x);
    float2 x23 = __half22float2(*(__half2*)&hv.y);
    float4 acc;
    acc.x = p*x01.x; acc.y = p*x01.y; acc.z = p*x23.x; acc.w = p*x23.y;

    // edges: 8 per chunk; lane computes exp for (edge e8, head hh)
    for (int base = beg; base < end; base += 8){
        int cnt = end - base; if (cnt > 8) cnt = 8;
        int s = 0; float pe = 0.f;
        if (e8 < cnt){
            s = d_csrc[base + e8];
            pe = __expf(lrelu(d_asn[s*4 + hh] + adh));
        }
        for (int j = 0; j < cnt; j++){
            int   sj = __shfl_sync(FULL, s, j);
            float pv = __shfl_sync(FULL, pe, j | (lane & 24));
            ssum += pv;
            uint2 h2 = *(const uint2*)(d_xph + (size_t)sj*HD + lane*4);
            float2 a01 = __half22float2(*(__half2*)&h2.x);
            float2 a23 = __half22float2(*(__half2*)&h2.y);
            acc.x += pv*a01.x; acc.y += pv*a01.y;
            acc.z += pv*a23.x; acc.w += pv*a23.y;
        }
    }
    float inv = 1.f / (ssum + 1e-16f);

    float4 bl4 = *(const float4*)(bl + lane*4);
    float t0 = acc.x*inv + bl4.x, t1 = acc.y*inv + bl4.y;
    float t2 = acc.z*inv + bl4.z, t3 = acc.w*inv + bl4.w;

    float ls = t0 + t1 + t2 + t3;
    #pragma unroll
    for (int o = 16; o; o >>= 1) ls += __shfl_xor_sync(FULL, ls, o);
    float mu = ls * (1.f/128.f);
    float dx0 = t0-mu, dx1 = t1-mu, dx2 = t2-mu, dx3 = t3-mu;
    float vq = dx0*dx0 + dx1*dx1 + dx2*dx2 + dx3*dx3;
    #pragma unroll
    for (int o = 16; o; o >>= 1) vq += __shfl_xor_sync(FULL, vq, o);
    float rstd = rsqrtf(vq*(1.f/128.f) + 1e-5f);

    float4 g4 = *(const float4*)(lng + lane*4);
    float4 b4 = *(const float4*)(lnb + lane*4);
    float cr  = d_crit[n];
    float4 hold = *(float4*)(d_h + (size_t)n*HD + lane*4);
    float4 outv;
    outv.x = dx0*rstd*g4.x + b4.x + cr + hold.x;
    outv.y = dx1*rstd*g4.y + b4.y + cr + hold.y;
    outv.z = dx2*rstd*g4.z + b4.z + cr + hold.z;
    outv.w = dx3*rstd*g4.w + b4.w + cr + hold.w;
    *(float4*)(d_h + (size_t)n*HD + lane*4) = outv;
}

// ---------------- fused gate head: d_gate = tanh(h@Wg1+bg1)·Wg2 + bg2 -----
__global__ void k_gatehead(const float* __restrict__ Wg1, const float* __restrict__ bg1,
                           const float* __restrict__ Wg2, const float* __restrict__ bg2){
    __shared__ float As[128][64];
    const int tid = threadIdx.x;
    const int tx = tid & 31, ty = tid >> 5;
    const int row0 = blockIdx.x * 64;

    {   // stage d_h transposed
        int r = tid >> 1;
        int halfk = (tid & 1) * 64;
        int grow = row0 + r;
        #pragma unroll
        for (int q = 0; q < 16; q++){
            float4 v = make_float4(0.f,0.f,0.f,0.f);
            if (grow < NN) v = *(const float4*)(d_h + (size_t)grow*128 + halfk + q*4);
            As[halfk + q*4 + 0][r] = v.x;
            As[halfk + q*4 + 1][r] = v.y;
            As[halfk + q*4 + 2][r] = v.z;
            As[halfk + q*4 + 3][r] = v.w;
        }
    }
    __syncthreads();

    unsigned long long acc2[8][2];
    #pragma unroll
    for (int r = 0; r < 8; r++){ acc2[r][0] = 0ull; acc2[r][1] = 0ull; }
    const int col = tx * 2;
    #pragma unroll 2
    for (int k = 0; k < 128; k++){
        float2 b = *(const float2*)(Wg1 + (size_t)k*64 + col);
        unsigned long long b0 = packdup(b.x), b1 = packdup(b.y);
        const ulonglong2* ap = (const ulonglong2*)&As[k][ty*16];
        #pragma unroll
        for (int r4 = 0; r4 < 4; r4++){
            ulonglong2 a2 = ap[r4];
            ffma2(acc2[2*r4  ][0], a2.x, b0);
            ffma2(acc2[2*r4  ][1], a2.x, b1);
            ffma2(acc2[2*r4+1][0], a2.y, b0);
            ffma2(acc2[2*r4+1][1], a2.y, b1);
        }
    }
    float b0 = bg1[col], b1 = bg1[col+1];
    float w0 = Wg2[col], w1 = Wg2[col+1];
    float bg = bg2[0];
    #pragma unroll
    for (int r = 0; r < 8; r++){
        float2 c0 = unpack2(acc2[r][0]);
        float2 c1 = unpack2(acc2[r][1]);
        float glo = tanhf(c0.x + b0)*w0 + tanhf(c1.x + b1)*w1;
        float ghi = tanhf(c0.y + b0)*w0 + tanhf(c1.y + b1)*w1;
        #pragma unroll
        for (int o = 16; o; o >>= 1){
            glo += __shfl_xor_sync(FULL, glo, o);
            ghi += __shfl_xor_sync(FULL, ghi, o);
        }
        if (tx == 0){
            int row = row0 + ty*16 + 2*r;
            if (row < NN)     d_gate[row]   = glo + bg;
            if (row+1 < NN)   d_gate[row+1] = ghi + bg;
        }
    }
}

// ---------------- pooling: one block per graph (batch sorted) -------------
__device__ __forceinline__ int lbound(const int* a, int n, int key){
    int lo = 0, hi = n;
    while (lo < hi){ int mid = (lo+hi)>>1; if (a[mid] < key) lo = mid+1; else hi = mid; }
    return lo;
}
__global__ void k_pool(const int* __restrict__ batch, float* __restrict__ out){
    int b = blockIdx.x, c = threadIdx.x;
    int lo = lbound(batch, NN, b), hi = lbound(batch, NN, b+1);
    float m = -3.402823e38f;
    for (int n = lo; n < hi; n++) m = fmaxf(m, d_gate[n]);
    float acc = 0.f, ps = 0.f;
    for (int n = lo; n < hi; n++){
        float p = expf(d_gate[n] - m);
        ps += p; acc += p * d_h[(size_t)n*HD + c];
    }
    out[b*HD + c] = acc / (ps + 1e-16f);
}

// ---------------- launch ----------------
extern "C" void kernel_launch(void* const* d_in, const int* in_sizes, int n_in,
                              void* d_out, int out_size){
    const float* x    = (const float*)d_in[0];
    const float* ea   = (const float*)d_in[1];
    const float* Win  = (const float*)d_in[2];
    const float* b_in = (const float*)d_in[3];
    const float* We1  = (const float*)d_in[4];
    const float* be1  = (const float*)d_in[5];
    const float* We2  = (const float*)d_in[6];
    const float* be2  = (const float*)d_in[7];
    const float* Wl   = (const float*)d_in[8];
    const float* asrc = (const float*)d_in[9];
    const float* adst = (const float*)d_in[10];
    const float* bl   = (const float*)d_in[11];
    const float* lng  = (const float*)d_in[12];
    const float* lnb  = (const float*)d_in[13];
    const float* Wg1  = (const float*)d_in[14];
    const float* bg1  = (const float*)d_in[15];
    const float* Wg2  = (const float*)d_in[16];
    const float* bg2  = (const float*)d_in[17];
    const int*   ei   = (const int*)d_in[18];
    const int*   batch= (const int*)d_in[19];
    float* out = (float*)d_out;

    const int EB  = (EE + 255)/256;
    const int NWB = (NN*32 + 255)/256;
    const int GB  = (NN + 63)/64;

    k_init<<<(NN+255)/256, 256>>>();
    k_edgemlp<<<EB, 256>>>(ea, ei, We1, be1, We2, be2);
    k_gemm128<0,0,1,0><<<GB, 256>>>(x, Win, b_in, (const float*)0, (const float*)0);
    k_gemm128<1,1,0,1><<<GB, 256>>>((const float*)0, Wl, (const float*)0, asrc, adst);

    // CSR build (independent of GEMMs)
    k_scan1<<<SCAN_BLOCKS, 256>>>();
    k_scan2<<<1, 256>>>();
    k_scan3<<<SCAN_BLOCKS, 256>>>();
    k_scatter<<<EB, 256>>>(ei);

    k_agg<<<NWB, 256>>>(bl, lng, lnb);
    for (int l = 1; l < 4; l++){
        k_gemm128<1,1,0,1><<<GB, 256>>>((const float*)0, Wl + (size_t)l*HD*HD,
                                        (const float*)0, asrc + l*128, adst + l*128);
        k_agg<<<NWB, 256>>>(bl + l*HD, lng + l*HD, lnb + l*HD);
    }

    k_gatehead<<<GB, 128>>>(Wg1, bg1, Wg2, bg2);
    k_pool<<<BB, 128>>>(batch, out);
}